// round 16
// baseline (speedup 1.0000x reference)
#include <cuda_runtime.h>
#include <cuda_fp16.h>

#define BB   4
#define CC   256
#define NN   4096
#define GG   8
#define NH   8
#define HD   32
#define MSEQ 512
#define OC3  768
// 1/sqrt(32) * log2(e): Q pre-scale so softmax runs in log2 domain (ex2)
#define Q2SCALE (0.17677669529663687f * 1.4426950408889634f)

typedef unsigned long long u64;
typedef unsigned int u32;
typedef __half f16;

// ---------------------------------------------------------------- helpers
__device__ __forceinline__ u32 smem_u32(const void* p) {
    u32 a; asm("{.reg .u64 t; cvta.to.shared.u64 t,%1; cvt.u32.u64 %0,t;}" : "=r"(a) : "l"(p));
    return a;
}
__device__ __forceinline__ void cpa16(u32 dst, const void* src) {
    asm volatile("cp.async.cg.shared.global [%0],[%1],16;" :: "r"(dst), "l"(src));
}
#define CPA_COMMIT() asm volatile("cp.async.commit_group;" ::: "memory")
#define CPA_WAIT1()  asm volatile("cp.async.wait_group 1;" ::: "memory")
#define CPA_WAIT0()  asm volatile("cp.async.wait_group 0;" ::: "memory")
// PDL primitives (sm_90+)
__device__ __forceinline__ void pdl_wait() {
    asm volatile("griddepcontrol.wait;" ::: "memory");
}
__device__ __forceinline__ void pdl_trigger() {
    asm volatile("griddepcontrol.launch_dependents;" ::: "memory");
}
__device__ __forceinline__ float ex2f(float x) {
    float r; asm("ex2.approx.f32 %0,%1;" : "=f"(r) : "f"(x)); return r;
}
// pack (lo, hi) f32 -> f16x2 in one cvt
__device__ __forceinline__ u32 cvtf16x2(float hi, float lo) {
    u32 r; asm("cvt.rn.f16x2.f32 %0,%1,%2;" : "=r"(r) : "f"(hi), "f"(lo)); return r;
}
__device__ __forceinline__ u32 ex2h2(u32 x) {
    u32 r; asm("ex2.approx.f16x2 %0,%1;" : "=r"(r) : "r"(x)); return r;
}
__device__ __forceinline__ void ldsm4(u32* r, u32 addr) {
    asm volatile("ldmatrix.sync.aligned.m8n8.x4.shared.b16 {%0,%1,%2,%3},[%4];"
                 : "=r"(r[0]), "=r"(r[1]), "=r"(r[2]), "=r"(r[3]) : "r"(addr));
}
__device__ __forceinline__ void ldsm4t(u32* r, u32 addr) {
    asm volatile("ldmatrix.sync.aligned.m8n8.x4.trans.shared.b16 {%0,%1,%2,%3},[%4];"
                 : "=r"(r[0]), "=r"(r[1]), "=r"(r[2]), "=r"(r[3]) : "r"(addr));
}
__device__ __forceinline__ void mma16816(float* d, const u32* a, const u32* b) {
    asm volatile("mma.sync.aligned.m16n8k16.row.col.f32.f16.f16.f32 "
                 "{%0,%1,%2,%3},{%4,%5,%6,%7},{%8,%9},{%0,%1,%2,%3};"
                 : "+f"(d[0]), "+f"(d[1]), "+f"(d[2]), "+f"(d[3])
                 : "r"(a[0]), "r"(a[1]), "r"(a[2]), "r"(a[3]), "r"(b[0]), "r"(b[1]));
}
__device__ __forceinline__ void st_h2(char* base, u32 off, f16 a, f16 b) {
    __half2 t; t.x = a; t.y = b;
    *reinterpret_cast<__half2*>(base + off) = t;
}

// chunk-32 tiles (qkv):
// A tile [128 m][32 k] f16: 64B rows, 4-chunk swizzle
__device__ __forceinline__ u32 a32_off(int m, int k8) {
    return m * 64 + ((((k8 >> 3) ^ ((m >> 1) & 3)) & 3) << 4);
}
// B tile [32 k][128 n] f16: 256B rows, 8-chunk swizzle
__device__ __forceinline__ u32 b32_off(int k, int n8) {
    return k * 256 + ((((n8 >> 3) ^ (k & 7))) << 4);
}
// chunk-64 tiles (proj):
__device__ __forceinline__ u32 a64_off(int m, int k8) {
    return m * 128 + ((((k8 >> 3) ^ (m & 7))) << 4);
}
__device__ __forceinline__ u32 b64_off(int k, int n8) {
    return k * 256 + ((((n8 >> 3) ^ (k & 7))) << 4);
}

// qkv smem: A 3 stages x 8KB @0 | B 2 bufs x 8KB @24576
#define QA_BASE 0
#define QB_BASE 24576
#define SMEM_QKV 40960
// proj smem (chunk 64, 3-stage)
#define ST_A    0
#define ST_B    16384
#define STAGE_SZ 32768
#define SMEM_GEMM (3 * STAGE_SZ)        // 98304

// ---------------- persistent f16 buffers
__device__ __align__(128) f16 gwq[OC3 * CC];
__device__ __align__(128) f16 gwp[CC * CC];
__device__ __align__(128) f16 gqkv[(size_t)BB * OC3 * NN];   // Q rows pre-scaled by Q2SCALE
__device__ __align__(128) f16 gatt[(size_t)BB * CC * NN];

// ---------------------------------------------------------------------------
// Tiny prepass: weights only, f32 -> f16.
// ---------------------------------------------------------------------------
#define N4Q (OC3 * CC / 4)
#define N4P (CC * CC / 4)

__global__ __launch_bounds__(256) void split_w_kernel(const float* __restrict__ wq,
                                                      const float* __restrict__ wp) {
    int i = blockIdx.x * blockDim.x + threadIdx.x;
    const float* src;
    f16* dst;
    int j;
    if (i < N4Q)            { src = wq; dst = gwq; j = i; }
    else if (i < N4Q + N4P) { src = wp; dst = gwp; j = i - N4Q; }
    else { pdl_trigger(); return; }
    float4 v = reinterpret_cast<const float4*>(src)[j];
    reinterpret_cast<uint2*>(dst)[j] =
        make_uint2(cvtf16x2(v.y, v.x), cvtf16x2(v.w, v.z));
    pdl_trigger();
}

// ---------------------------------------------------------------------------
// Kernel 1: qkv GEMM. A = gwq f16 (cp.async 3-stage). B = x f32 streamed
// on the fly: LDG f32 -> cvt -> STS, double-buffered smem, 1 barrier/chunk.
// ---------------------------------------------------------------------------
__global__ __launch_bounds__(256, 2) void qkv_gemm_kernel(const float* __restrict__ x) {
    extern __shared__ char smem[];
    const u32 sb = smem_u32(smem);
    const int t = threadIdx.x, wid = t >> 5, lane = t & 31;
    const int wm = (wid & 3) * 32, wn = (wid >> 2) * 64;
    const int b = blockIdx.z, n0 = blockIdx.x * 128, m0 = blockIdx.y * 128;
    const float* xb = x + (size_t)b * CC * NN + n0;

    float acc[2][8][4];
#pragma unroll
    for (int i = 0; i < 2; i++)
#pragma unroll
        for (int j = 0; j < 8; j++)
#pragma unroll
            for (int c = 0; c < 4; c++) acc[i][j][c] = 0.f;

    float tmpf[16];
    u32 bb[8];

    auto ldgB = [&](int ch) {
#pragma unroll
        for (int p = 0; p < 4; p++) {
            int idx = p * 256 + t;
            int k = idx >> 5, n4 = (idx & 31) * 4;
            float4 v = *reinterpret_cast<const float4*>(xb + (size_t)(ch * 32 + k) * NN + n4);
            tmpf[p * 4] = v.x; tmpf[p * 4 + 1] = v.y;
            tmpf[p * 4 + 2] = v.z; tmpf[p * 4 + 3] = v.w;
        }
    };
    auto cvtB = [&]() {
#pragma unroll
        for (int p = 0; p < 4; p++) {
            bb[p * 2]     = cvtf16x2(tmpf[p * 4 + 1], tmpf[p * 4]);
            bb[p * 2 + 1] = cvtf16x2(tmpf[p * 4 + 3], tmpf[p * 4 + 2]);
        }
    };
    auto stsB = [&](int buf) {
#pragma unroll
        for (int p = 0; p < 4; p++) {
            int idx = p * 256 + t;
            int k = idx >> 5, n4 = (idx & 31) * 4;
            u32 off = QB_BASE + buf * 8192 + b32_off(k, n4 & ~7) + (n4 & 7) * 2;
            u64 v = (u64)bb[p * 2] | ((u64)bb[p * 2 + 1] << 32);
            *reinterpret_cast<u64*>(smem + off) = v;
        }
    };
    auto cpaA = [&](int ch, int st) {
        u32 base = sb + QA_BASE + st * 8192;
#pragma unroll
        for (int p = 0; p < 2; p++) {
            int idx = p * 256 + t;
            int m = idx >> 2, k8 = (idx & 3) * 8;
            cpa16(base + a32_off(m, k8), gwq + (size_t)(m0 + m) * CC + ch * 32 + k8);
        }
    };

    // prologue: x loads (no dependency on split), then wait for weights
    ldgB(0); cvtB(); stsB(0);
    ldgB(1); cvtB();                  // bb = chunk 1
    pdl_wait();
    cpaA(0, 0); CPA_COMMIT();
    cpaA(1, 1); CPA_COMMIT();

    for (int ch = 0; ch < 8; ch++) {
        if (ch == 7) { CPA_WAIT0(); } else { CPA_WAIT1(); }
        __syncthreads();
        if (ch + 2 < 8) { cpaA(ch + 2, (ch + 2) % 3); CPA_COMMIT(); }
        if (ch + 1 < 8) stsB((ch + 1) & 1);
        if (ch + 2 < 8) ldgB(ch + 2);

        u32 abase = sb + QA_BASE + (ch % 3) * 8192;
        u32 bbase = sb + QB_BASE + (ch & 1) * 8192;
#pragma unroll
        for (int ks = 0; ks < 2; ks++) {
            u32 ah[2][4];
#pragma unroll
            for (int i = 0; i < 2; i++) {
                int row = wm + i * 16 + (lane & 15);
                int kc  = ks * 16 + (lane >> 4) * 8;
                u32 ao = row * 64 + ((((kc >> 3) ^ ((row >> 1) & 3)) & 3) << 4);
                ldsm4(ah[i], abase + ao);
            }
#pragma unroll
            for (int nh = 0; nh < 2; nh++) {
                u32 bh[2][4];
#pragma unroll
                for (int pp = 0; pp < 2; pp++) {
                    int k = ks * 16 + ((lane >> 3) & 1) * 8 + (lane & 7);
                    int nb = wn + nh * 32 + pp * 16 + (lane >> 4) * 8;
                    u32 bo = k * 256 + ((((nb >> 3) ^ (k & 7))) << 4);
                    ldsm4t(bh[pp], bbase + bo);
                }
#pragma unroll
                for (int i = 0; i < 2; i++)
#pragma unroll
                    for (int pp = 0; pp < 2; pp++)
#pragma unroll
                        for (int s = 0; s < 2; s++)
                            mma16816(acc[i][nh * 4 + pp * 2 + s], ah[i], bh[pp] + s * 2);
            }
        }
        if (ch + 2 < 8) cvtB();
    }

    // epilogue: store f16, Q rows pre-scaled
    f16* oh = gqkv + ((size_t)b * OC3 + m0) * NN + n0;
#pragma unroll
    for (int i = 0; i < 2; i++) {
        int r0 = wm + i * 16 + (lane >> 2);
        float s0 = (m0 + r0 < CC) ? Q2SCALE : 1.f;
        float s8 = (m0 + r0 + 8 < CC) ? Q2SCALE : 1.f;
#pragma unroll
        for (int nt = 0; nt < 8; nt++) {
            int n = wn + nt * 8 + (lane & 3) * 2;
            *reinterpret_cast<u32*>(oh + (size_t)r0 * NN + n) =
                cvtf16x2(acc[i][nt][1] * s0, acc[i][nt][0] * s0);
            *reinterpret_cast<u32*>(oh + (size_t)(r0 + 8) * NN + n) =
                cvtf16x2(acc[i][nt][3] * s8, acc[i][nt][2] * s8);
        }
    }
    pdl_trigger();
}

// ---------------------------------------------------------------------------
// proj GEMM (unchanged R15): 3-stage cp.async, K-chunk 64, PRE_A weight prefetch.
// ---------------------------------------------------------------------------
__global__ __launch_bounds__(256, 2) void proj_gemm_kernel(const float* __restrict__ bias,
                                                           float* __restrict__ out) {
    extern __shared__ char smem[];
    const u32 sb = smem_u32(smem);
    const int t = threadIdx.x, wid = t >> 5, lane = t & 31;
    const int wm = (wid & 3) * 32, wn = (wid >> 2) * 64;
    const int b = blockIdx.z, n0 = blockIdx.x * 128, m0 = blockIdx.y * 128;
    const f16* Ah = gwp;
    const f16* Bh = gatt + (size_t)b * CC * NN + n0;
    constexpr int NCH = CC / 64;

    float acc[2][8][4];
#pragma unroll
    for (int i = 0; i < 2; i++)
#pragma unroll
        for (int j = 0; j < 8; j++)
#pragma unroll
            for (int c = 0; c < 4; c++) acc[i][j][c] = 0.f;

    const int amb = t >> 3,  ak8 = (t & 7) * 8;
    const int bkb = t >> 4,  bn8 = (t & 15) * 8;

    auto fillA = [&](int c0, int buf) {
        u32 base = sb + buf * STAGE_SZ + ST_A;
#pragma unroll
        for (int p = 0; p < 4; p++) {
            int m = p * 32 + amb;
            cpa16(base + a64_off(m, ak8), Ah + (size_t)(m0 + m) * CC + c0 + ak8);
        }
    };
    auto fillB = [&](int c0, int buf) {
        u32 base = sb + buf * STAGE_SZ + ST_B;
#pragma unroll
        for (int p = 0; p < 4; p++) {
            int k = p * 16 + bkb;
            cpa16(base + b64_off(k, bn8), Bh + (size_t)(c0 + k) * NN + bn8);
        }
    };

    fillA(0, 0);                  // weights: safe before PDL edge
    pdl_wait();
    fillB(0, 0);  CPA_COMMIT();
    fillA(64, 1); fillB(64, 1); CPA_COMMIT();

    for (int ch = 0; ch < NCH; ch++) {
        if (ch == NCH - 1) { CPA_WAIT0(); } else { CPA_WAIT1(); }
        __syncthreads();
        if (ch + 2 < NCH) {
            fillA((ch + 2) * 64, (ch + 2) % 3);
            fillB((ch + 2) * 64, (ch + 2) % 3);
            CPA_COMMIT();
        }
        u32 base = sb + (ch % 3) * STAGE_SZ;

#pragma unroll
        for (int ks = 0; ks < 4; ks++) {
            u32 ah[2][4];
#pragma unroll
            for (int i = 0; i < 2; i++) {
                int row = wm + i * 16 + (lane & 15);
                int kc  = ks * 16 + (lane >> 4) * 8;
                u32 ao = row * 128 + ((((kc >> 3) ^ (row & 7))) << 4);
                ldsm4(ah[i], base + ST_A + ao);
            }
#pragma unroll
            for (int nh = 0; nh < 2; nh++) {
                u32 bh[2][4];
#pragma unroll
                for (int pp = 0; pp < 2; pp++) {
                    int k = ks * 16 + ((lane >> 3) & 1) * 8 + (lane & 7);
                    int nb = wn + nh * 32 + pp * 16 + (lane >> 4) * 8;
                    u32 bo = k * 256 + ((((nb >> 3) ^ (k & 7))) << 4);
                    ldsm4t(bh[pp], base + ST_B + bo);
                }
#pragma unroll
                for (int i = 0; i < 2; i++)
#pragma unroll
                    for (int pp = 0; pp < 2; pp++)
#pragma unroll
                        for (int s = 0; s < 2; s++)
                            mma16816(acc[i][nh * 4 + pp * 2 + s], ah[i], bh[pp] + s * 2);
            }
        }
    }

    float* outp = out + ((size_t)b * CC + m0) * NN + n0;
#pragma unroll
    for (int i = 0; i < 2; i++) {
        int r0 = wm + i * 16 + (lane >> 2);
        float b0 = bias[m0 + r0], b8 = bias[m0 + r0 + 8];
#pragma unroll
        for (int nt = 0; nt < 8; nt++) {
            int n = wn + nt * 8 + (lane & 3) * 2;
            float* d0 = outp + (size_t)r0 * NN + n;
            *reinterpret_cast<float2*>(d0) =
                make_float2(acc[i][nt][0] + b0, acc[i][nt][1] + b0);
            *reinterpret_cast<float2*>(d0 + 8 * NN) =
                make_float2(acc[i][nt][2] + b8, acc[i][nt][3] + b8);
        }
    }
}

// ---------------------------------------------------------------------------
// Kernel 2: grouped MHA (unchanged R15). 128 queries/block, 8 warps.
// ---------------------------------------------------------------------------
#define AK 0
#define AV 4096
#define ASTG 8192
#define SMEM_ATT (8192 + 3 * ASTG)      // 32768

__global__ __launch_bounds__(256) void attn_kernel() {
    extern __shared__ char sm[];
    char* Qs = sm;
    float* Os = reinterpret_cast<float*>(sm + 8192);
    const u32 sb = smem_u32(sm);

    const int t = threadIdx.x, lane = t & 31, wid = t >> 5;
    const int head = blockIdx.y;
    const int b = head >> 6, g = (head >> 3) & 7, hh = head & 7;
    const int nqbase = g * MSEQ + blockIdx.x * 128;
    const size_t qoff = ((size_t)b * OC3 + hh * HD) * NN;
    const f16* qp = gqkv + qoff;
    const f16* kp = qp + (size_t)CC * NN;
    const f16* vp = qp + (size_t)(2 * CC) * NN;

    const int fd = t >> 3, fk8 = (t & 7) * 8;
    const u32 fo = fd * 128 + ((((fk8 >> 3) ^ (fd & 7))) << 4);

    auto fill_kv = [&](int kt, int buf) {
        const int nk = g * MSEQ + kt * 64;
        u32 base = sb + 8192 + buf * ASTG;
        size_t s = (size_t)fd * NN + nk + fk8;
        cpa16(base + AK + fo, kp + s);
        cpa16(base + AV + fo, vp + s);
    };

    pdl_wait();

    fill_kv(0, 0); CPA_COMMIT();
    fill_kv(1, 1); CPA_COMMIT();

    {
        int q = t & 127, dh = (t >> 7) * 16;
        const f16* ph = qp + nqbase + q;
#pragma unroll
        for (int dd = 0; dd < 16; dd += 2) {
            int d = dh + dd;
            u32 off = q * 64 + ((((d >> 3) ^ ((q >> 1) & 3)) & 3) << 4) + (d & 7) * 2;
            st_h2(Qs, off, ph[(size_t)d * NN], ph[(size_t)(d + 1) * NN]);
        }
    }
    __syncthreads();

    u32 qh[2][4];
    {
        int row = wid * 16 + (lane & 15);
#pragma unroll
        for (int ks = 0; ks < 2; ks++) {
            int kc = ks * 16 + (lane >> 4) * 8;
            u32 ao = row * 64 + ((((kc >> 3) ^ ((row >> 1) & 3)) & 3) << 4);
            ldsm4(qh[ks], sb + ao);
        }
    }

    float oacc[4][4];
    float oaccl[4];
#pragma unroll
    for (int i = 0; i < 4; i++) {
        oaccl[i] = 0.f;
#pragma unroll
        for (int j = 0; j < 4; j++) oacc[i][j] = 0.f;
    }
    const u32 ones2[2] = {0x3C003C00u, 0x3C003C00u};
    float mx0 = -1e30f, mx1 = -1e30f;

    for (int kt = 0; kt < 8; kt++) {
        if (kt == 7) { CPA_WAIT0(); } else { CPA_WAIT1(); }
        __syncthreads();
        if (kt + 2 < 8) { fill_kv(kt + 2, (kt + 2) % 3); CPA_COMMIT(); }
        u32 base = sb + 8192 + (kt % 3) * ASTG;

        float sacc[8][4];
#pragma unroll
        for (int i = 0; i < 8; i++)
#pragma unroll
            for (int j = 0; j < 4; j++) sacc[i][j] = 0.f;
#pragma unroll
        for (int ks = 0; ks < 2; ks++) {
            int kd = ks * 16 + ((lane >> 3) & 1) * 8 + (lane & 7);
            u32 krb = kd * 128;
#pragma unroll
            for (int pp = 0; pp < 4; pp++) {
                int nb = pp * 16 + (lane >> 4) * 8;
                u32 off = krb + ((((nb >> 3) ^ (kd & 7))) << 4);
                u32 kbh[4];
                ldsm4t(kbh, base + AK + off);
#pragma unroll
                for (int s = 0; s < 2; s++)
                    mma16816(sacc[pp * 2 + s], qh[ks], kbh + s * 2);
            }
        }

        float rm0 = -1e30f, rm1 = -1e30f;
#pragma unroll
        for (int j = 0; j < 8; j++) {
            rm0 = fmaxf(rm0, fmaxf(sacc[j][0], sacc[j][1]));
            rm1 = fmaxf(rm1, fmaxf(sacc[j][2], sacc[j][3]));
        }
        rm0 = fmaxf(rm0, __shfl_xor_sync(0xffffffffu, rm0, 1));
        rm0 = fmaxf(rm0, __shfl_xor_sync(0xffffffffu, rm0, 2));
        rm1 = fmaxf(rm1, __shfl_xor_sync(0xffffffffu, rm1, 1));
        rm1 = fmaxf(rm1, __shfl_xor_sync(0xffffffffu, rm1, 2));
        float nm0 = fmaxf(mx0, rm0), nm1 = fmaxf(mx1, rm1);
        float c0 = ex2f(mx0 - nm0), c1 = ex2f(mx1 - nm1);
        mx0 = nm0; mx1 = nm1;
#pragma unroll
        for (int df = 0; df < 4; df++) {
            oacc[df][0] *= c0; oacc[df][1] *= c0;
            oacc[df][2] *= c1; oacc[df][3] *= c1;
        }
        oaccl[0] *= c0; oaccl[1] *= c0;
        oaccl[2] *= c1; oaccl[3] *= c1;

        u32 aph[4][4];
#pragma unroll
        for (int j = 0; j < 8; j++) {
            int ks = j >> 1, half = (j & 1) * 2;
            aph[ks][half] =
                ex2h2(cvtf16x2(sacc[j][1] - nm0, sacc[j][0] - nm0));
            aph[ks][half + 1] =
                ex2h2(cvtf16x2(sacc[j][3] - nm1, sacc[j][2] - nm1));
        }

#pragma unroll
        for (int ks = 0; ks < 4; ks++)
            mma16816(oaccl, aph[ks], ones2);

#pragma unroll
        for (int ks = 0; ks < 4; ks++) {
            int kk = ks * 16 + ((lane >> 3) & 1) * 8;
#pragma unroll
            for (int dg = 0; dg < 2; dg++) {
                int dn = dg * 16 + (lane >> 4) * 8 + (lane & 7);
                u32 off = dn * 128 + ((((kk >> 3) ^ (dn & 7))) << 4);
                u32 vbh[4];
                ldsm4(vbh, base + AV + off);
#pragma unroll
                for (int s = 0; s < 2; s++)
                    mma16816(oacc[dg * 2 + s], aph[ks], vbh + s * 2);
            }
        }
    }

    float inv0 = 1.f / oaccl[0], inv1 = 1.f / oaccl[2];
    __syncthreads();
    {
        int r = wid * 16 + (lane >> 2);
#pragma unroll
        for (int df = 0; df < 4; df++) {
            int dc = df * 8 + (lane & 3) * 2;
            *reinterpret_cast<float2*>(&Os[r * 34 + dc]) =
                make_float2(oacc[df][0] * inv0, oacc[df][1] * inv0);
            *reinterpret_cast<float2*>(&Os[(r + 8) * 34 + dc]) =
                make_float2(oacc[df][2] * inv1, oacc[df][3] * inv1);
        }
    }
    __syncthreads();
    {
        int d = t >> 3, qg = (t & 7) * 16;
        f16* dh_ = gatt + ((size_t)b * CC + hh * HD + d) * NN + nqbase + qg;
#pragma unroll
        for (int qq = 0; qq < 16; qq += 2) {
            *reinterpret_cast<u32*>(dh_ + qq) =
                cvtf16x2(Os[(qg + qq + 1) * 34 + d], Os[(qg + qq) * 34 + d]);
        }
    }
    pdl_trigger();
}

// ---------------------------------------------------------------------------
extern "C" void kernel_launch(void* const* d_in, const int* in_sizes, int n_in,
                              void* d_out, int out_size) {
    const float* x      = (const float*)d_in[0];
    const float* w_qkv  = (const float*)d_in[1];
    const float* w_proj = (const float*)d_in[2];
    const float* b_proj = (const float*)d_in[3];
    float* out = (float*)d_out;

    cudaFuncSetAttribute(qkv_gemm_kernel, cudaFuncAttributeMaxDynamicSharedMemorySize, SMEM_QKV);
    cudaFuncSetAttribute(proj_gemm_kernel, cudaFuncAttributeMaxDynamicSharedMemorySize, SMEM_GEMM);
    cudaFuncSetAttribute(attn_kernel, cudaFuncAttributeMaxDynamicSharedMemorySize, SMEM_ATT);

    // launch 0: weight split (tiny)
    split_w_kernel<<<(N4Q + N4P + 255) / 256, 256>>>(w_qkv, w_proj);

    cudaLaunchAttribute at[1];
    at[0].id = cudaLaunchAttributeProgrammaticStreamSerialization;
    at[0].val.programmaticStreamSerializationAllowed = 1;

    // launch 1: qkv (PDL on split_w; x loads issued pre-wait)
    {
        cudaLaunchConfig_t cfg = {};
        cfg.gridDim  = dim3(NN / 128, OC3 / 128, BB);
        cfg.blockDim = dim3(256, 1, 1);
        cfg.dynamicSmemBytes = SMEM_QKV;
        cfg.attrs = at; cfg.numAttrs = 1;
        cudaLaunchKernelEx(&cfg, qkv_gemm_kernel, x);
    }
    // launch 2: attn (PDL on qkv)
    {
        cudaLaunchConfig_t cfg = {};
        cfg.gridDim  = dim3(MSEQ / 128, BB * GG * NH, 1);
        cfg.blockDim = dim3(256, 1, 1);
        cfg.dynamicSmemBytes = SMEM_ATT;
        cfg.attrs = at; cfg.numAttrs = 1;
        cudaLaunchKernelEx(&cfg, attn_kernel);
    }
    // launch 3: proj (PDL on attn; weight stage prefetched pre-wait)
    {
        cudaLaunchConfig_t cfg = {};
        cfg.gridDim  = dim3(NN / 128, CC / 128, BB);
        cfg.blockDim = dim3(256, 1, 1);
        cfg.dynamicSmemBytes = SMEM_GEMM;
        cfg.attrs = at; cfg.numAttrs = 1;
        cudaLaunchKernelEx(&cfg, proj_gemm_kernel, b_proj, out);
    }
}

// round 17
// speedup vs baseline: 1.0785x; 1.0785x over previous
#include <cuda_runtime.h>
#include <cuda_fp16.h>

#define BB   4
#define CC   256
#define NN   4096
#define GG   8
#define NH   8
#define HD   32
#define MSEQ 512
#define OC3  768
// 1/sqrt(32) * log2(e): Q pre-scale so softmax runs in log2 domain (ex2)
#define Q2SCALE (0.17677669529663687f * 1.4426950408889634f)

typedef unsigned long long u64;
typedef unsigned int u32;
typedef __half f16;

// ---------------------------------------------------------------- helpers
__device__ __forceinline__ u32 smem_u32(const void* p) {
    u32 a; asm("{.reg .u64 t; cvta.to.shared.u64 t,%1; cvt.u32.u64 %0,t;}" : "=r"(a) : "l"(p));
    return a;
}
__device__ __forceinline__ void cpa16(u32 dst, const void* src) {
    asm volatile("cp.async.cg.shared.global [%0],[%1],16;" :: "r"(dst), "l"(src));
}
#define CPA_COMMIT() asm volatile("cp.async.commit_group;" ::: "memory")
#define CPA_WAIT2()  asm volatile("cp.async.wait_group 2;" ::: "memory")
#define CPA_WAIT1()  asm volatile("cp.async.wait_group 1;" ::: "memory")
#define CPA_WAIT0()  asm volatile("cp.async.wait_group 0;" ::: "memory")
// PDL primitives (sm_90+)
__device__ __forceinline__ void pdl_wait() {
    asm volatile("griddepcontrol.wait;" ::: "memory");
}
__device__ __forceinline__ void pdl_trigger() {
    asm volatile("griddepcontrol.launch_dependents;" ::: "memory");
}
__device__ __forceinline__ float ex2f(float x) {
    float r; asm("ex2.approx.f32 %0,%1;" : "=f"(r) : "f"(x)); return r;
}
// pack (lo, hi) f32 -> f16x2 in one cvt
__device__ __forceinline__ u32 cvtf16x2(float hi, float lo) {
    u32 r; asm("cvt.rn.f16x2.f32 %0,%1,%2;" : "=r"(r) : "f"(hi), "f"(lo)); return r;
}
__device__ __forceinline__ u32 ex2h2(u32 x) {
    u32 r; asm("ex2.approx.f16x2 %0,%1;" : "=r"(r) : "r"(x)); return r;
}
__device__ __forceinline__ void ldsm4(u32* r, u32 addr) {
    asm volatile("ldmatrix.sync.aligned.m8n8.x4.shared.b16 {%0,%1,%2,%3},[%4];"
                 : "=r"(r[0]), "=r"(r[1]), "=r"(r[2]), "=r"(r[3]) : "r"(addr));
}
__device__ __forceinline__ void ldsm4t(u32* r, u32 addr) {
    asm volatile("ldmatrix.sync.aligned.m8n8.x4.trans.shared.b16 {%0,%1,%2,%3},[%4];"
                 : "=r"(r[0]), "=r"(r[1]), "=r"(r[2]), "=r"(r[3]) : "r"(addr));
}
__device__ __forceinline__ void mma16816(float* d, const u32* a, const u32* b) {
    asm volatile("mma.sync.aligned.m16n8k16.row.col.f32.f16.f16.f32 "
                 "{%0,%1,%2,%3},{%4,%5,%6,%7},{%8,%9},{%0,%1,%2,%3};"
                 : "+f"(d[0]), "+f"(d[1]), "+f"(d[2]), "+f"(d[3])
                 : "r"(a[0]), "r"(a[1]), "r"(a[2]), "r"(a[3]), "r"(b[0]), "r"(b[1]));
}
__device__ __forceinline__ void st_h2(char* base, u32 off, f16 a, f16 b) {
    __half2 t; t.x = a; t.y = b;
    *reinterpret_cast<__half2*>(base + off) = t;
}

// GEMM tiles, K-chunk 64:
// A tile [128 m][64 k] f16: 128B rows, 8-chunk swizzle
__device__ __forceinline__ u32 a64_off(int m, int k8) {
    return m * 128 + ((((k8 >> 3) ^ (m & 7))) << 4);
}
// B tile [64 k][128 n] f16: 256B rows, 8-chunk swizzle
__device__ __forceinline__ u32 b64_off(int k, int n8) {
    return k * 256 + ((((n8 >> 3) ^ (k & 7))) << 4);
}

#define ST_A    0
#define ST_B    16384
#define STAGE_SZ 32768
#define SMEM_GEMM (3 * STAGE_SZ)        // 98304, 3-stage, K-chunk 64

// ---------------- persistent f16 buffers (plain fp16, fp32 accum in mma)
__device__ __align__(128) f16 gx[(size_t)BB * CC * NN];
__device__ __align__(128) f16 gwq[OC3 * CC];
__device__ __align__(128) f16 gwp[CC * CC];
__device__ __align__(128) f16 gqkv[(size_t)BB * OC3 * NN];   // Q rows pre-scaled by Q2SCALE
__device__ __align__(128) f16 gatt[(size_t)BB * CC * NN];

// ---------------------------------------------------------------------------
// Fused prepass: f32 -> f16 for x, w_qkv, w_proj in one launch.
// ---------------------------------------------------------------------------
#define N4X (BB * CC * NN / 4)
#define N4Q (OC3 * CC / 4)
#define N4P (CC * CC / 4)

__global__ __launch_bounds__(256) void split_all_kernel(const float* __restrict__ x,
                                                        const float* __restrict__ wq,
                                                        const float* __restrict__ wp) {
    int i = blockIdx.x * blockDim.x + threadIdx.x;
    const float* src;
    f16* hi;
    int j;
    if (i < N4X)                  { src = x;  hi = gx;  j = i; }
    else if (i < N4X + N4Q)       { src = wq; hi = gwq; j = i - N4X; }
    else if (i < N4X + N4Q + N4P) { src = wp; hi = gwp; j = i - N4X - N4Q; }
    else { pdl_trigger(); return; }
    float4 v = reinterpret_cast<const float4*>(src)[j];
    reinterpret_cast<uint2*>(hi)[j] =
        make_uint2(cvtf16x2(v.y, v.x), cvtf16x2(v.w, v.z));
    pdl_trigger();
}

// ---------------------------------------------------------------------------
// GEMM mainloop: 3-stage cp.async, K-chunks of 64, plain fp16 operands.
// PRE_A: issue first A-stage loads BEFORE pdl_wait (A independent of producer).
// ---------------------------------------------------------------------------
template<int KDIM, bool PRE_A>
__device__ __forceinline__ void gemm_main(const f16* __restrict__ Ah,
                                          const f16* __restrict__ Bh,
                                          size_t ldb, int m0, char* smem,
                                          float (&acc)[2][8][4]) {
    const u32 sb = smem_u32(smem);
    const int t = threadIdx.x;
    const int wid = t >> 5, lane = t & 31;
    const int wm = (wid & 3) * 32;
    const int wn = (wid >> 2) * 64;
    constexpr int NCH = KDIM / 64;

#pragma unroll
    for (int i = 0; i < 2; i++)
#pragma unroll
        for (int j = 0; j < 8; j++)
#pragma unroll
            for (int c = 0; c < 4; c++) acc[i][j][c] = 0.f;

    const int amb = t >> 3,  ak8 = (t & 7) * 8;     // A: m = p*32 + amb
    const int bkb = t >> 4,  bn8 = (t & 15) * 8;    // B: k = p*16 + bkb

    auto fillA = [&](int c0, int buf) {
        u32 base = sb + buf * STAGE_SZ + ST_A;
#pragma unroll
        for (int p = 0; p < 4; p++) {
            int m = p * 32 + amb;
            cpa16(base + a64_off(m, ak8), Ah + (size_t)(m0 + m) * KDIM + c0 + ak8);
        }
    };
    auto fillB = [&](int c0, int buf) {
        u32 base = sb + buf * STAGE_SZ + ST_B;
#pragma unroll
        for (int p = 0; p < 4; p++) {
            int k = p * 16 + bkb;
            cpa16(base + b64_off(k, bn8), Bh + (size_t)(c0 + k) * ldb + bn8);
        }
    };

    if (PRE_A) {
        fillA(0, 0);                  // weights: safe before PDL edge
        pdl_wait();
        fillB(0, 0);  CPA_COMMIT();
        fillA(64, 1); fillB(64, 1); CPA_COMMIT();
    } else {
        pdl_wait();
        fillA(0, 0);  fillB(0, 0);  CPA_COMMIT();
        fillA(64, 1); fillB(64, 1); CPA_COMMIT();
    }

    for (int ch = 0; ch < NCH; ch++) {
        if (ch == NCH - 1) { CPA_WAIT0(); } else { CPA_WAIT1(); }
        __syncthreads();
        if (ch + 2 < NCH) {
            fillA((ch + 2) * 64, (ch + 2) % 3);
            fillB((ch + 2) * 64, (ch + 2) % 3);
            CPA_COMMIT();
        }
        u32 base = sb + (ch % 3) * STAGE_SZ;

#pragma unroll
        for (int ks = 0; ks < 4; ks++) {
            u32 ah[2][4];
#pragma unroll
            for (int i = 0; i < 2; i++) {
                int row = wm + i * 16 + (lane & 15);
                int kc  = ks * 16 + (lane >> 4) * 8;
                u32 ao = row * 128 + ((((kc >> 3) ^ (row & 7))) << 4);
                ldsm4(ah[i], base + ST_A + ao);
            }
#pragma unroll
            for (int nh = 0; nh < 2; nh++) {
                u32 bh[2][4];
#pragma unroll
                for (int pp = 0; pp < 2; pp++) {
                    int k = ks * 16 + ((lane >> 3) & 1) * 8 + (lane & 7);
                    int nb = wn + nh * 32 + pp * 16 + (lane >> 4) * 8;
                    u32 bo = k * 256 + ((((nb >> 3) ^ (k & 7))) << 4);
                    ldsm4t(bh[pp], base + ST_B + bo);
                }
#pragma unroll
                for (int i = 0; i < 2; i++)
#pragma unroll
                    for (int pp = 0; pp < 2; pp++)
#pragma unroll
                        for (int s = 0; s < 2; s++)
                            mma16816(acc[i][nh * 4 + pp * 2 + s], ah[i], bh[pp] + s * 2);
            }
        }
    }
}

// Kernel 1: qkv GEMM -> f16, Q rows pre-scaled by Q2SCALE
__global__ __launch_bounds__(256, 2) void qkv_gemm_kernel() {
    extern __shared__ char smem[];
    const int b = blockIdx.z;
    const int n0 = blockIdx.x * 128;
    const int m0 = blockIdx.y * 128;
    float acc[2][8][4];
    gemm_main<CC, false>(gwq, gx + (size_t)b * CC * NN + n0, NN, m0, smem, acc);

    const int t = threadIdx.x, wid = t >> 5, lane = t & 31;
    const int wm = (wid & 3) * 32, wn = (wid >> 2) * 64;
    f16* oh = gqkv + ((size_t)b * OC3 + m0) * NN + n0;
#pragma unroll
    for (int i = 0; i < 2; i++) {
        int r0 = wm + i * 16 + (lane >> 2);
        float s0 = (m0 + r0 < CC) ? Q2SCALE : 1.f;
        float s8 = (m0 + r0 + 8 < CC) ? Q2SCALE : 1.f;
#pragma unroll
        for (int nt = 0; nt < 8; nt++) {
            int n = wn + nt * 8 + (lane & 3) * 2;
            *reinterpret_cast<u32*>(oh + (size_t)r0 * NN + n) =
                cvtf16x2(acc[i][nt][1] * s0, acc[i][nt][0] * s0);
            *reinterpret_cast<u32*>(oh + (size_t)(r0 + 8) * NN + n) =
                cvtf16x2(acc[i][nt][3] * s8, acc[i][nt][2] * s8);
        }
    }
    pdl_trigger();
}

// Kernel 3: proj GEMM + bias -> f32 out (weights prefetched before PDL wait)
__global__ __launch_bounds__(256, 2) void proj_gemm_kernel(const float* __restrict__ bias,
                                                           float* __restrict__ out) {
    extern __shared__ char smem[];
    const int b = blockIdx.z;
    const int n0 = blockIdx.x * 128;
    const int m0 = blockIdx.y * 128;
    float acc[2][8][4];
    gemm_main<CC, true>(gwp, gatt + (size_t)b * CC * NN + n0, NN, m0, smem, acc);

    const int t = threadIdx.x, wid = t >> 5, lane = t & 31;
    const int wm = (wid & 3) * 32, wn = (wid >> 2) * 64;
    float* outp = out + ((size_t)b * CC + m0) * NN + n0;
#pragma unroll
    for (int i = 0; i < 2; i++) {
        int r0 = wm + i * 16 + (lane >> 2);
        float b0 = bias[m0 + r0], b8 = bias[m0 + r0 + 8];
#pragma unroll
        for (int nt = 0; nt < 8; nt++) {
            int n = wn + nt * 8 + (lane & 3) * 2;
            float* d0 = outp + (size_t)r0 * NN + n;
            *reinterpret_cast<float2*>(d0) =
                make_float2(acc[i][nt][0] + b0, acc[i][nt][1] + b0);
            *reinterpret_cast<float2*>(d0 + 8 * NN) =
                make_float2(acc[i][nt][2] + b8, acc[i][nt][3] + b8);
        }
    }
}

// ---------------------------------------------------------------------------
// Kernel 2: grouped MHA, plain fp16. 128 queries/block, 8 warps.
// 4-stage cp.async ring: fill for kt+2 issued BEFORE wait/barrier (safe with
// 4 stages: target stage last read at kt-2, fenced by kt-1's barrier).
// P via ex2.approx.f16x2; row-sum l via ones-MMA. Tile-0 rescale peeled.
// dyn smem: Qs 8KB @0 | stages @8192 + s*8192 (K 4KB, V 4KB). Os overlays.
// ---------------------------------------------------------------------------
#define AK 0
#define AV 4096
#define ASTG 8192
#define SMEM_ATT (8192 + 4 * ASTG)      // 40960

__global__ __launch_bounds__(256) void attn_kernel() {
    extern __shared__ char sm[];
    char* Qs = sm;
    float* Os = reinterpret_cast<float*>(sm + 8192);
    const u32 sb = smem_u32(sm);

    const int t = threadIdx.x, lane = t & 31, wid = t >> 5;
    const int head = blockIdx.y;
    const int b = head >> 6, g = (head >> 3) & 7, hh = head & 7;
    const int nqbase = g * MSEQ + blockIdx.x * 128;
    const size_t qoff = ((size_t)b * OC3 + hh * HD) * NN;
    const f16* qp = gqkv + qoff;
    const f16* kp = qp + (size_t)CC * NN;
    const f16* vp = qp + (size_t)(2 * CC) * NN;

    const int fd = t >> 3, fk8 = (t & 7) * 8;
    const u32 fo = fd * 128 + ((((fk8 >> 3) ^ (fd & 7))) << 4);

    auto fill_kv = [&](int kt, int buf) {
        const int nk = g * MSEQ + kt * 64;
        u32 base = sb + 8192 + buf * ASTG;
        size_t s = (size_t)fd * NN + nk + fk8;
        cpa16(base + AK + fo, kp + s);
        cpa16(base + AV + fo, vp + s);
    };

    pdl_wait();

    fill_kv(0, 0); CPA_COMMIT();
    fill_kv(1, 1); CPA_COMMIT();

    // ---- Q fill: transpose [d][n] -> smem [q][d] (64B rows, 4-chunk swizzle)
    {
        int q = t & 127, dh = (t >> 7) * 16;
        const f16* ph = qp + nqbase + q;
#pragma unroll
        for (int dd = 0; dd < 16; dd += 2) {
            int d = dh + dd;
            u32 off = q * 64 + ((((d >> 3) ^ ((q >> 1) & 3)) & 3) << 4) + (d & 7) * 2;
            st_h2(Qs, off, ph[(size_t)d * NN], ph[(size_t)(d + 1) * NN]);
        }
    }
    __syncthreads();

    u32 qh[2][4];
    {
        int row = wid * 16 + (lane & 15);
#pragma unroll
        for (int ks = 0; ks < 2; ks++) {
            int kc = ks * 16 + (lane >> 4) * 8;
            u32 ao = row * 64 + ((((kc >> 3) ^ ((row >> 1) & 3)) & 3) << 4);
            ldsm4(qh[ks], sb + ao);
        }
    }

    float oacc[4][4];
    float oaccl[4];                       // l accumulator (ones-MMA)
#pragma unroll
    for (int i = 0; i < 4; i++) {
        oaccl[i] = 0.f;
#pragma unroll
        for (int j = 0; j < 4; j++) oacc[i][j] = 0.f;
    }
    const u32 ones2[2] = {0x3C003C00u, 0x3C003C00u};   // f16x2 {1,1}
    float mx0 = -1e30f, mx1 = -1e30f;

    for (int kt = 0; kt < 8; kt++) {
        // prefetch kt+2 BEFORE wait/barrier (4-stage ring makes this safe)
        if (kt + 2 < 8) { fill_kv(kt + 2, (kt + 2) & 3); CPA_COMMIT(); }
        if (kt < 6)      { CPA_WAIT2(); }
        else if (kt == 6){ CPA_WAIT1(); }
        else             { CPA_WAIT0(); }
        __syncthreads();
        u32 base = sb + 8192 + (kt & 3) * ASTG;

        // ---- S = Q K^T (log2-domain; Q pre-scaled)
        float sacc[8][4];
#pragma unroll
        for (int i = 0; i < 8; i++)
#pragma unroll
            for (int j = 0; j < 4; j++) sacc[i][j] = 0.f;
#pragma unroll
        for (int ks = 0; ks < 2; ks++) {
            int kd = ks * 16 + ((lane >> 3) & 1) * 8 + (lane & 7);
            u32 krb = kd * 128;
#pragma unroll
            for (int pp = 0; pp < 4; pp++) {
                int nb = pp * 16 + (lane >> 4) * 8;
                u32 off = krb + ((((nb >> 3) ^ (kd & 7))) << 4);
                u32 kbh[4];
                ldsm4t(kbh, base + AK + off);
#pragma unroll
                for (int s = 0; s < 2; s++)
                    mma16816(sacc[pp * 2 + s], qh[ks], kbh + s * 2);
            }
        }

        // ---- online softmax (base-2); tile 0 peeled (no rescale needed)
        float rm0 = -1e30f, rm1 = -1e30f;
#pragma unroll
        for (int j = 0; j < 8; j++) {
            rm0 = fmaxf(rm0, fmaxf(sacc[j][0], sacc[j][1]));
            rm1 = fmaxf(rm1, fmaxf(sacc[j][2], sacc[j][3]));
        }
        rm0 = fmaxf(rm0, __shfl_xor_sync(0xffffffffu, rm0, 1));
        rm0 = fmaxf(rm0, __shfl_xor_sync(0xffffffffu, rm0, 2));
        rm1 = fmaxf(rm1, __shfl_xor_sync(0xffffffffu, rm1, 1));
        rm1 = fmaxf(rm1, __shfl_xor_sync(0xffffffffu, rm1, 2));
        float nm0, nm1;
        if (kt == 0) {
            nm0 = rm0; nm1 = rm1;
            mx0 = nm0; mx1 = nm1;
        } else {
            nm0 = fmaxf(mx0, rm0); nm1 = fmaxf(mx1, rm1);
            float c0 = ex2f(mx0 - nm0), c1 = ex2f(mx1 - nm1);
            mx0 = nm0; mx1 = nm1;
#pragma unroll
            for (int df = 0; df < 4; df++) {
                oacc[df][0] *= c0; oacc[df][1] *= c0;
                oacc[df][2] *= c1; oacc[df][3] *= c1;
            }
            oaccl[0] *= c0; oaccl[1] *= c0;
            oaccl[2] *= c1; oaccl[3] *= c1;
        }

        u32 aph[4][4];
#pragma unroll
        for (int j = 0; j < 8; j++) {
            int ks = j >> 1, half = (j & 1) * 2;
            aph[ks][half] =
                ex2h2(cvtf16x2(sacc[j][1] - nm0, sacc[j][0] - nm0));
            aph[ks][half + 1] =
                ex2h2(cvtf16x2(sacc[j][3] - nm1, sacc[j][2] - nm1));
        }

        // ---- row-sum l via ones-MMA
#pragma unroll
        for (int ks = 0; ks < 4; ks++)
            mma16816(oaccl, aph[ks], ones2);

        // ---- O += P V  (V in [d][key], NON-trans ldsm)
#pragma unroll
        for (int ks = 0; ks < 4; ks++) {
            int kk = ks * 16 + ((lane >> 3) & 1) * 8;
#pragma unroll
            for (int dg = 0; dg < 2; dg++) {
                int dn = dg * 16 + (lane >> 4) * 8 + (lane & 7);
                u32 off = dn * 128 + ((((kk >> 3) ^ (dn & 7))) << 4);
                u32 vbh[4];
                ldsm4(vbh, base + AV + off);
#pragma unroll
                for (int s = 0; s < 2; s++)
                    mma16816(oacc[dg * 2 + s], aph[ks], vbh + s * 2);
            }
        }
    }

    // ---- epilogue: normalize (l from ones-MMA accumulator), stage, store f16
    float inv0 = 1.f / oaccl[0], inv1 = 1.f / oaccl[2];
    __syncthreads();
    {
        int r = wid * 16 + (lane >> 2);
#pragma unroll
        for (int df = 0; df < 4; df++) {
            int dc = df * 8 + (lane & 3) * 2;
            *reinterpret_cast<float2*>(&Os[r * 34 + dc]) =
                make_float2(oacc[df][0] * inv0, oacc[df][1] * inv0);
            *reinterpret_cast<float2*>(&Os[(r + 8) * 34 + dc]) =
                make_float2(oacc[df][2] * inv1, oacc[df][3] * inv1);
        }
    }
    __syncthreads();
    {
        int d = t >> 3, qg = (t & 7) * 16;
        f16* dh_ = gatt + ((size_t)b * CC + hh * HD + d) * NN + nqbase + qg;
#pragma unroll
        for (int qq = 0; qq < 16; qq += 2) {
            *reinterpret_cast<u32*>(dh_ + qq) =
                cvtf16x2(Os[(qg + qq + 1) * 34 + d], Os[(qg + qq) * 34 + d]);
        }
    }
    pdl_trigger();
}

// ---------------------------------------------------------------------------
extern "C" void kernel_launch(void* const* d_in, const int* in_sizes, int n_in,
                              void* d_out, int out_size) {
    const float* x      = (const float*)d_in[0];
    const float* w_qkv  = (const float*)d_in[1];
    const float* w_proj = (const float*)d_in[2];
    const float* b_proj = (const float*)d_in[3];
    float* out = (float*)d_out;

    cudaFuncSetAttribute(qkv_gemm_kernel, cudaFuncAttributeMaxDynamicSharedMemorySize, SMEM_GEMM);
    cudaFuncSetAttribute(proj_gemm_kernel, cudaFuncAttributeMaxDynamicSharedMemorySize, SMEM_GEMM);
    cudaFuncSetAttribute(attn_kernel, cudaFuncAttributeMaxDynamicSharedMemorySize, SMEM_ATT);

    // launch 0: split (no PDL dependency upstream)
    split_all_kernel<<<(N4X + N4Q + N4P + 255) / 256, 256>>>(x, w_qkv, w_proj);

    cudaLaunchAttribute at[1];
    at[0].id = cudaLaunchAttributeProgrammaticStreamSerialization;
    at[0].val.programmaticStreamSerializationAllowed = 1;

    // launch 1: qkv (PDL on split)
    {
        cudaLaunchConfig_t cfg = {};
        cfg.gridDim  = dim3(NN / 128, OC3 / 128, BB);
        cfg.blockDim = dim3(256, 1, 1);
        cfg.dynamicSmemBytes = SMEM_GEMM;
        cfg.attrs = at; cfg.numAttrs = 1;
        cudaLaunchKernelEx(&cfg, qkv_gemm_kernel);
    }
    // launch 2: attn (PDL on qkv)
    {
        cudaLaunchConfig_t cfg = {};
        cfg.gridDim  = dim3(MSEQ / 128, BB * GG * NH, 1);
        cfg.blockDim = dim3(256, 1, 1);
        cfg.dynamicSmemBytes = SMEM_ATT;
        cfg.attrs = at; cfg.numAttrs = 1;
        cudaLaunchKernelEx(&cfg, attn_kernel);
    }
    // launch 3: proj (PDL on attn; weight stage prefetched pre-wait)
    {
        cudaLaunchConfig_t cfg = {};
        cfg.gridDim  = dim3(NN / 128, CC / 128, BB);
        cfg.blockDim = dim3(256, 1, 1);
        cfg.dynamicSmemBytes = SMEM_GEMM;
        cfg.attrs = at; cfg.numAttrs = 1;
        cudaLaunchKernelEx(&cfg, proj_gemm_kernel, b_proj, out);
    }
}